// round 14
// baseline (speedup 1.0000x reference)
#include <cuda_runtime.h>
#include <cuda_fp16.h>
#include <cstdint>

#define Nn 50000
#define NnP 50048
#define Ee 400000
#define Kk 512
#define Hh 8
#define Ff 64
#define HFt 512
#define NEG 0.2f

#define M0_BLKS 196                    // M quarter split: 196 + 195 = 391
#define M1_BLKS 195
#define M0_ROWS (M0_BLKS * 128)        // 25088

// ---------------- device scratch ----------------
__device__ __align__(16) __half g_featv[(size_t)Nn * HFt];   // 51.2 MB fp16
__device__ __align__(16) __half g_Ah[(size_t)NnP * Kk];      // feat fp16
__device__ __align__(16) __half g_Bh[HFt * Kk];              // W_val^T fp16 [N][K]
__device__ float g_el[Nn * Hh];
__device__ float g_er[Nn * Hh];
__device__ float g_u[Kk * 16];
__device__ float g_c[16];
__device__ int   g_deg[Nn];
__device__ int   g_row[Nn + 1];
__device__ int   g_pos[Nn];
__device__ int   g_csrc[Ee];
__device__ int   g_part[64];

// ---------------- ptx helpers ----------------
__device__ __forceinline__ uint32_t smem_u32(const void* p) {
    uint32_t a;
    asm("{ .reg .u64 t; cvta.to.shared.u64 t, %1; cvt.u32.u64 %0, t; }" : "=r"(a) : "l"(p));
    return a;
}
__device__ __forceinline__ void cpa16(uint32_t d, const void* s) {
    asm volatile("cp.async.cg.shared.global [%0], [%1], 16;" :: "r"(d), "l"(s));
}
__device__ __forceinline__ void cp_commit() {
    asm volatile("cp.async.commit_group;" ::: "memory");
}
template<int NN>
__device__ __forceinline__ void cp_wait() {
    asm volatile("cp.async.wait_group %0;" :: "n"(NN) : "memory");
}
__device__ __forceinline__ void ldmx4(uint32_t& r0, uint32_t& r1, uint32_t& r2, uint32_t& r3, uint32_t a) {
    asm volatile("ldmatrix.sync.aligned.m8n8.x4.shared.b16 {%0,%1,%2,%3}, [%4];"
                 : "=r"(r0), "=r"(r1), "=r"(r2), "=r"(r3) : "r"(a));
}
__device__ __forceinline__ void mma16816(float* d, const uint32_t* a, uint32_t b0, uint32_t b1) {
    asm volatile("mma.sync.aligned.m16n8k16.row.col.f32.f16.f16.f32 "
                 "{%0,%1,%2,%3}, {%4,%5,%6,%7}, {%8,%9}, {%0,%1,%2,%3};"
                 : "+f"(d[0]), "+f"(d[1]), "+f"(d[2]), "+f"(d[3])
                 : "r"(a[0]), "r"(a[1]), "r"(a[2]), "r"(a[3]), "r"(b0), "r"(b1));
}

// ---------------- zero deg + part ----------------
__global__ void k_zdeg() {
    int i = blockIdx.x * 256 + threadIdx.x;
    if (i < Nn) g_deg[i] = 0;
    if (blockIdx.x == 0 && threadIdx.x < 64) g_part[threadIdx.x] = 0;
}

// ---------------- setup: prep (u,c) + W_val transpose (weights only) ----------------
__global__ void k_setup(const float* __restrict__ Wsrc, const float* __restrict__ Wdst,
                        const float* __restrict__ al, const float* __restrict__ ar,
                        const float* __restrict__ bsrc, const float* __restrict__ bdst,
                        const float* __restrict__ Wval) {
    int b = blockIdx.x, tid = threadIdx.x;
    if (b < 32) {
        int id = b * 256 + tid;
        int k = id >> 4, j = id & 15, h = j & 7;
        const float* W = (j < 8) ? Wsrc : Wdst;
        const float* a = (j < 8) ? al : ar;
        float s = 0.f;
        #pragma unroll 8
        for (int f = 0; f < Ff; f++) s += W[k * HFt + h * Ff + f] * a[h * Ff + f];
        g_u[k * 16 + j] = s;
        if (id < 16) {
            const float* bb = (j < 8) ? bsrc : bdst;
            float s2 = 0.f;
            for (int f = 0; f < Ff; f++) s2 += bb[h * Ff + f] * a[h * Ff + f];
            g_c[id] = s2;
        }
    } else {
        int idx = (b - 32) * 256 + tid;          // [n][k]
        int n = idx >> 9, k = idx & 511;
        g_Bh[idx] = __float2half_rn(Wval[k * HFt + n]);
    }
}

// ---------------- feat -> fp16 + edge histogram (row-range split) ----------------
// quadBase: starting float4 index. Histogram fires for global idx < Ee
// (entirely inside the first split since M0_ROWS*128 >> Ee).
__global__ void __launch_bounds__(256) k_convert(const float* __restrict__ feat,
                                                 const int* __restrict__ dst,
                                                 size_t quadBase) {
    size_t idx = quadBase + (size_t)blockIdx.x * 256 + threadIdx.x;
    if (idx < Ee) atomicAdd(&g_deg[dst[idx]], 1);
    size_t row = idx >> 7;
    float4 v = make_float4(0.f, 0.f, 0.f, 0.f);
    if (row < Nn) v = ((const float4*)feat)[idx];
    __half2 h0 = __floats2half2_rn(v.x, v.y);
    __half2 h1 = __floats2half2_rn(v.z, v.w);
    ((uint2*)g_Ah)[idx] = make_uint2(*reinterpret_cast<uint32_t*>(&h0),
                                     *reinterpret_cast<uint32_t*>(&h1));
}

// ---------------- 2-phase scan ----------------
__global__ void k_scan1() {
    __shared__ int sh[1024];
    int t = threadIdx.x;
    int i = blockIdx.x * 1024 + t;
    int v = (i < Nn) ? g_deg[i] : 0;
    sh[t] = v;
    __syncthreads();
    for (int off = 1; off < 1024; off <<= 1) {
        int x = (t >= off) ? sh[t - off] : 0;
        __syncthreads();
        sh[t] += x;
        __syncthreads();
    }
    if (i < Nn) g_row[i] = sh[t] - v;
    if (t == 1023) g_part[blockIdx.x] = sh[1023];
}
__global__ void k_scan3(int nblk) {
    __shared__ int sp[64];
    int t = threadIdx.x;
    if (t < 64) sp[t] = g_part[t];
    __syncthreads();
    int off = 0, total = 0;
    #pragma unroll
    for (int i = 0; i < 64; i++) {
        int v = sp[i];
        total += v;
        if (i < blockIdx.x) off += v;
    }
    int i = blockIdx.x * 1024 + t;
    if (i < Nn) {
        int x = g_row[i] + off;
        g_row[i] = x;
        g_pos[i] = x;
    }
    if (blockIdx.x == nblk - 1 && t == 0) g_row[Nn] = total;
}

__global__ void k_scatter(const int* __restrict__ src, const int* __restrict__ dst) {
    int e = blockIdx.x * blockDim.x + threadIdx.x;
    if (e < Ee) {
        int d = dst[e];
        int slot = atomicAdd(&g_pos[d], 1);
        g_csrc[slot] = src[e];
    }
}

// ---------------- skinny GEMM: el/er = feat(fp16) @ u + c ----------------
__global__ void __launch_bounds__(128) k_elr() {
    __shared__ float sA[128][33];
    __shared__ float sB[32][16];
    int tid = threadIdx.x;
    int rowBase = blockIdx.x * 128;
    float acc[16];
    #pragma unroll
    for (int j = 0; j < 16; j++) acc[j] = g_c[j];

    for (int kt = 0; kt < Kk; kt += 32) {
        #pragma unroll
        for (int i = 0; i < 8; i++) {
            int f4 = i * 128 + tid;
            int r = f4 >> 3, c4 = f4 & 7;
            uint2 u = ((const uint2*)g_Ah)[((size_t)(rowBase + r) * Kk + kt + c4 * 4) >> 2];
            float2 a = __half22float2(*reinterpret_cast<__half2*>(&u.x));
            float2 bb = __half22float2(*reinterpret_cast<__half2*>(&u.y));
            sA[r][c4 * 4 + 0] = a.x;  sA[r][c4 * 4 + 1] = a.y;
            sA[r][c4 * 4 + 2] = bb.x; sA[r][c4 * 4 + 3] = bb.y;
        }
        {
            int r = tid >> 2, c4 = tid & 3;
            float4 v = *(const float4*)&g_u[(kt + r) * 16 + c4 * 4];
            *(float4*)&sB[r][c4 * 4] = v;
        }
        __syncthreads();
        #pragma unroll
        for (int k = 0; k < 32; k++) {
            float f = sA[tid][k];
            float4 b0 = *(float4*)&sB[k][0];
            float4 b1 = *(float4*)&sB[k][4];
            float4 b2 = *(float4*)&sB[k][8];
            float4 b3 = *(float4*)&sB[k][12];
            acc[0] += f * b0.x; acc[1] += f * b0.y; acc[2] += f * b0.z; acc[3] += f * b0.w;
            acc[4] += f * b1.x; acc[5] += f * b1.y; acc[6] += f * b1.z; acc[7] += f * b1.w;
            acc[8] += f * b2.x; acc[9] += f * b2.y; acc[10] += f * b2.z; acc[11] += f * b2.w;
            acc[12] += f * b3.x; acc[13] += f * b3.y; acc[14] += f * b3.z; acc[15] += f * b3.w;
        }
        __syncthreads();
    }
    int n = rowBase + tid;
    if (n < Nn) {
        #pragma unroll
        for (int h = 0; h < 8; h++) {
            g_el[n * 8 + h] = acc[h];
            g_er[n * 8 + h] = acc[8 + h];
        }
    }
}

// ---------------- HMMA GEMM quarter: M-range x N-half ----------------
#define PITCH 144
#define MAT_B (128 * PITCH)
#define STAGE_B (2 * MAT_B)
#define SMEM_GEMM (2 * STAGE_B)        // 73728

__global__ void __launch_bounds__(256, 2) k_gemm_mma(const float* __restrict__ bias,
                                                     int mOff, int nOff) {
    extern __shared__ char sm[];
    uint32_t sb = smem_u32(sm);

    const int tid = threadIdx.x;
    const int lane = tid & 31, wid = tid >> 5;
    const int wm = wid >> 1, wn = wid & 1;           // warp grid 4x2
    const int mBase = (blockIdx.y + mOff) * 128;
    const int nBase = (blockIdx.x + nOff) * 128;

    const int g8 = lane >> 3, lr = lane & 7;
    const int a_row = lr + ((g8 == 1 || g8 == 3) ? 8 : 0);
    const uint32_t a_kb = (g8 >= 2) ? 16 : 0;
    const int b_row = lr + ((g8 >= 2) ? 8 : 0);
    const uint32_t b_kb = (g8 & 1) ? 16 : 0;
    const uint32_t aAddr0 = sb + 0 * MAT_B + (wm * 32 + a_row) * PITCH + a_kb;
    const uint32_t bAddr0 = sb + 1 * MAT_B + (wn * 64 + b_row) * PITCH + b_kb;

    float acc[2][8][4];
    #pragma unroll
    for (int i = 0; i < 2; i++)
        #pragma unroll
        for (int j = 0; j < 8; j++)
            #pragma unroll
            for (int q = 0; q < 4; q++) acc[i][j][q] = 0.f;

    const __half* gp_i[8];
    uint32_t sd_i[8];
    #pragma unroll
    for (int i = 0; i < 8; i++) {
        int idx = tid + i * 256;
        int mat = idx >> 10;
        int rc = idx & 1023;
        int r = rc >> 3, ch = rc & 7;
        const __half* base = (mat == 0) ? g_Ah : g_Bh;
        int rowG = ((mat == 0) ? mBase : nBase) + r;
        gp_i[i] = base + (size_t)rowG * Kk + ch * 8;
        sd_i[i] = sb + mat * MAT_B + r * PITCH + ch * 16;
    }
    auto load_stage = [&](int c, int buf) {
        uint32_t bo = buf * STAGE_B;
        #pragma unroll
        for (int i = 0; i < 8; i++) cpa16(sd_i[i] + bo, gp_i[i] + c * 64);
    };

    load_stage(0, 0);
    cp_commit();

    for (int c = 0; c < 8; c++) {
        cp_wait<0>();
        __syncthreads();
        if (c + 1 < 8) {
            load_stage(c + 1, (c + 1) & 1);
            cp_commit();
        }

        const uint32_t stOff = (c & 1) * STAGE_B;
        #pragma unroll
        for (int ks = 0; ks < 4; ks++) {
            uint32_t kb = stOff + ks * 32;
            uint32_t ah[2][4], bh[4][4];
            #pragma unroll
            for (int mt = 0; mt < 2; mt++)
                ldmx4(ah[mt][0], ah[mt][1], ah[mt][2], ah[mt][3], aAddr0 + kb + mt * 16 * PITCH);
            #pragma unroll
            for (int nt = 0; nt < 4; nt++)
                ldmx4(bh[nt][0], bh[nt][1], bh[nt][2], bh[nt][3], bAddr0 + kb + nt * 16 * PITCH);
            #pragma unroll
            for (int mt = 0; mt < 2; mt++)
                #pragma unroll
                for (int nt = 0; nt < 4; nt++) {
                    mma16816(acc[mt][2 * nt + 0], ah[mt], bh[nt][0], bh[nt][1]);
                    mma16816(acc[mt][2 * nt + 1], ah[mt], bh[nt][2], bh[nt][3]);
                }
        }
    }

    const int qr = lane >> 2, qc = (lane & 3) * 2;
    #pragma unroll
    for (int mt = 0; mt < 2; mt++) {
        int row0 = mBase + wm * 32 + mt * 16 + qr;
        #pragma unroll
        for (int n8 = 0; n8 < 8; n8++) {
            int col = nBase + wn * 64 + n8 * 8 + qc;
            float bx = bias[col], by = bias[col + 1];
            if (row0 < Nn) {
                __half2 o = __floats2half2_rn(acc[mt][n8][0] + bx, acc[mt][n8][1] + by);
                *(__half2*)&g_featv[(size_t)row0 * HFt + col] = o;
            }
            if (row0 + 8 < Nn) {
                __half2 o = __floats2half2_rn(acc[mt][n8][2] + bx, acc[mt][n8][3] + by);
                *(__half2*)&g_featv[(size_t)(row0 + 8) * HFt + col] = o;
            }
        }
    }
}

// ---------------- per-dst softmax + aggregation (head-half via hOff) ----------------
__global__ void __launch_bounds__(256) k_agg(float* __restrict__ out, int hOff) {
    int grp = threadIdx.x >> 6;                 // 4 nodes per block
    int n = blockIdx.x * 4 + grp;
    if (n >= Nn) return;
    int t = threadIdx.x & 63;
    int h = (t >> 4) + hOff;
    int colBase = h * 64 + (t & 15) * 4;

    int beg = g_row[n], end = g_row[n + 1];
    float er = g_er[n * 8 + h];

    float ssum = 0.f;
    for (int j = beg; j < end; j++) {
        float e = g_el[g_csrc[j] * 8 + h] + er;
        e = (e >= 0.f) ? e : NEG * e;
        ssum += __expf(e);
    }
    float rs = 1.0f / fmaxf(ssum, 1e-16f);

    float4 acc = make_float4(0.f, 0.f, 0.f, 0.f);
    int j = beg;
    for (; j + 2 <= end; j += 2) {
        int s0 = g_csrc[j], s1 = g_csrc[j + 1];
        float e0 = g_el[s0 * 8 + h] + er;
        float e1 = g_el[s1 * 8 + h] + er;
        e0 = (e0 >= 0.f) ? e0 : NEG * e0;
        e1 = (e1 >= 0.f) ? e1 : NEG * e1;
        float a0 = __expf(e0) * rs;
        float a1 = __expf(e1) * rs;
        uint2 u0 = *(const uint2*)&g_featv[(size_t)s0 * HFt + colBase];
        uint2 u1 = *(const uint2*)&g_featv[(size_t)s1 * HFt + colBase];
        float2 p0 = __half22float2(*(__half2*)&u0.x);
        float2 p1 = __half22float2(*(__half2*)&u0.y);
        float2 q0 = __half22float2(*(__half2*)&u1.x);
        float2 q1 = __half22float2(*(__half2*)&u1.y);
        acc.x += a0 * p0.x + a1 * q0.x;
        acc.y += a0 * p0.y + a1 * q0.y;
        acc.z += a0 * p1.x + a1 * q1.x;
        acc.w += a0 * p1.y + a1 * q1.y;
    }
    if (j < end) {
        int s0 = g_csrc[j];
        float e0 = g_el[s0 * 8 + h] + er;
        e0 = (e0 >= 0.f) ? e0 : NEG * e0;
        float a0 = __expf(e0) * rs;
        uint2 u0 = *(const uint2*)&g_featv[(size_t)s0 * HFt + colBase];
        float2 p0 = __half22float2(*(__half2*)&u0.x);
        float2 p1 = __half22float2(*(__half2*)&u0.y);
        acc.x += a0 * p0.x; acc.y += a0 * p0.y; acc.z += a0 * p1.x; acc.w += a0 * p1.y;
    }
    *(float4*)&out[(size_t)n * HFt + colBase] = acc;
}

// ---------------- launch: quartered GEMM pipeline ----------------
extern "C" void kernel_launch(void* const* d_in, const int* in_sizes, int n_in,
                              void* d_out, int out_size) {
    const float* feat = (const float*)d_in[0];
    const int*   src  = (const int*)d_in[1];
    const int*   dst  = (const int*)d_in[2];
    const float* Wsrc = (const float*)d_in[3];
    const float* bsrc = (const float*)d_in[4];
    const float* Wdst = (const float*)d_in[5];
    const float* bdst = (const float*)d_in[6];
    const float* Wval = (const float*)d_in[7];
    const float* bval = (const float*)d_in[8];
    const float* al   = (const float*)d_in[9];
    const float* ar   = (const float*)d_in[10];
    float* out = (float*)d_out;

    static cudaStream_t s1 = nullptr;
    static cudaEvent_t evRoot = nullptr, evSetup = nullptr, evC0 = nullptr, evC1 = nullptr,
                       evSide = nullptr, evN0 = nullptr, evA0 = nullptr;
    if (!s1) {
        cudaFuncSetAttribute(k_gemm_mma, cudaFuncAttributeMaxDynamicSharedMemorySize, SMEM_GEMM);
        cudaStreamCreateWithFlags(&s1, cudaStreamNonBlocking);
        cudaEventCreateWithFlags(&evRoot, cudaEventDisableTiming);
        cudaEventCreateWithFlags(&evSetup, cudaEventDisableTiming);
        cudaEventCreateWithFlags(&evC0, cudaEventDisableTiming);
        cudaEventCreateWithFlags(&evC1, cudaEventDisableTiming);
        cudaEventCreateWithFlags(&evSide, cudaEventDisableTiming);
        cudaEventCreateWithFlags(&evN0, cudaEventDisableTiming);
        cudaEventCreateWithFlags(&evA0, cudaEventDisableTiming);
    }

    int nscan = (Nn + 1023) / 1024;
    const size_t C0_QUADS = (size_t)M0_ROWS * 128;                // rows [0, 25088)
    const size_t C1_QUADS = (size_t)(NnP - M0_ROWS) * 128;        // rows [25088, 50048)

    // main: zero deg (capture root)
    k_zdeg<<<196, 256>>>();
    cudaEventRecord(evRoot, 0);

    // side: setup (weights), then convert upper M-half
    cudaStreamWaitEvent(s1, evRoot, 0);
    k_setup<<<1056, 256, 0, s1>>>(Wsrc, Wdst, al, ar, bsrc, bdst, Wval);
    cudaEventRecord(evSetup, s1);
    k_convert<<<(int)(C1_QUADS / 256), 256, 0, s1>>>(feat, dst, C0_QUADS);
    cudaEventRecord(evC1, s1);

    // main: convert lower M-half (includes ALL edge histogram work)
    k_convert<<<(int)(C0_QUADS / 256), 256>>>(feat, dst, 0);
    cudaEventRecord(evC0, 0);

    // main: GEMM quarters. N0 first so agg heads [0,4) can start early.
    cudaStreamWaitEvent(0, evSetup, 0);
    k_gemm_mma<<<dim3(2, M0_BLKS), 256, SMEM_GEMM>>>(bval, 0, 0);       // M0 x N0
    cudaStreamWaitEvent(0, evC1, 0);
    k_gemm_mma<<<dim3(2, M1_BLKS), 256, SMEM_GEMM>>>(bval, M0_BLKS, 0); // M1 x N0
    cudaEventRecord(evN0, 0);
    k_gemm_mma<<<dim3(2, M0_BLKS), 256, SMEM_GEMM>>>(bval, 0, 2);       // M0 x N1
    k_gemm_mma<<<dim3(2, M1_BLKS), 256, SMEM_GEMM>>>(bval, M0_BLKS, 2); // M1 x N1

    // side: CSR build + edge logits (histogram done at evC0; g_Ah complete after C1 in-stream)
    cudaStreamWaitEvent(s1, evC0, 0);
    k_scan1<<<nscan, 1024, 0, s1>>>();
    k_scan3<<<nscan, 1024, 0, s1>>>(nscan);
    k_scatter<<<(Ee + 255) / 256, 256, 0, s1>>>(src, dst);
    k_elr<<<NnP / 128, 128, 0, s1>>>();
    cudaEventRecord(evSide, s1);

    // side: agg heads [0,4) overlaps GEMM N1 quarters
    cudaStreamWaitEvent(s1, evN0, 0);
    k_agg<<<(Nn + 3) / 4, 256, 0, s1>>>(out, 0);
    cudaEventRecord(evA0, s1);

    // main: agg heads [4,8) after N1 + side chain
    cudaStreamWaitEvent(0, evSide, 0);
    k_agg<<<(Nn + 3) / 4, 256>>>(out, 4);

    // join
    cudaStreamWaitEvent(0, evA0, 0);
}

// round 15
// speedup vs baseline: 1.1936x; 1.1936x over previous
#include <cuda_runtime.h>
#include <cuda_fp16.h>
#include <cstdint>

#define Nn 50000
#define NnP 50048
#define Ee 400000
#define Kk 512
#define Hh 8
#define Ff 64
#define HFt 512
#define NEG 0.2f

// ---------------- device scratch ----------------
__device__ __align__(16) __half g_featv[(size_t)Nn * HFt];   // 51.2 MB fp16
__device__ __align__(16) __half g_Ah[(size_t)NnP * Kk];      // feat fp16
__device__ __align__(16) __half g_Bh[HFt * Kk];              // W_val^T fp16 [N][K]
__device__ float g_el[Nn * Hh];
__device__ float g_er[Nn * Hh];
__device__ float g_u[Kk * 16];
__device__ float g_c[16];
__device__ int   g_deg[Nn];
__device__ int   g_row[Nn + 1];
__device__ int   g_pos[Nn];
__device__ int   g_csrc[Ee];
__device__ int   g_part[64];

// ---------------- ptx helpers ----------------
__device__ __forceinline__ uint32_t smem_u32(const void* p) {
    uint32_t a;
    asm("{ .reg .u64 t; cvta.to.shared.u64 t, %1; cvt.u32.u64 %0, t; }" : "=r"(a) : "l"(p));
    return a;
}
__device__ __forceinline__ void cpa16(uint32_t d, const void* s) {
    asm volatile("cp.async.cg.shared.global [%0], [%1], 16;" :: "r"(d), "l"(s));
}
__device__ __forceinline__ void cp_commit() {
    asm volatile("cp.async.commit_group;" ::: "memory");
}
template<int NN>
__device__ __forceinline__ void cp_wait() {
    asm volatile("cp.async.wait_group %0;" :: "n"(NN) : "memory");
}
__device__ __forceinline__ void ldmx4(uint32_t& r0, uint32_t& r1, uint32_t& r2, uint32_t& r3, uint32_t a) {
    asm volatile("ldmatrix.sync.aligned.m8n8.x4.shared.b16 {%0,%1,%2,%3}, [%4];"
                 : "=r"(r0), "=r"(r1), "=r"(r2), "=r"(r3) : "r"(a));
}
__device__ __forceinline__ void mma16816(float* d, const uint32_t* a, uint32_t b0, uint32_t b1) {
    asm volatile("mma.sync.aligned.m16n8k16.row.col.f32.f16.f16.f32 "
                 "{%0,%1,%2,%3}, {%4,%5,%6,%7}, {%8,%9}, {%0,%1,%2,%3};"
                 : "+f"(d[0]), "+f"(d[1]), "+f"(d[2]), "+f"(d[3])
                 : "r"(a[0]), "r"(a[1]), "r"(a[2]), "r"(a[3]), "r"(b0), "r"(b1));
}

// ---------------- zero deg + part ----------------
__global__ void k_zdeg() {
    int i = blockIdx.x * 256 + threadIdx.x;
    if (i < Nn) g_deg[i] = 0;
    if (blockIdx.x == 0 && threadIdx.x < 64) g_part[threadIdx.x] = 0;
}

// ---------------- setup: prep (u,c) + W_val transpose (weights only) ----------------
__global__ void k_setup(const float* __restrict__ Wsrc, const float* __restrict__ Wdst,
                        const float* __restrict__ al, const float* __restrict__ ar,
                        const float* __restrict__ bsrc, const float* __restrict__ bdst,
                        const float* __restrict__ Wval) {
    int b = blockIdx.x, tid = threadIdx.x;
    if (b < 32) {
        int id = b * 256 + tid;
        int k = id >> 4, j = id & 15, h = j & 7;
        const float* W = (j < 8) ? Wsrc : Wdst;
        const float* a = (j < 8) ? al : ar;
        float s = 0.f;
        #pragma unroll 8
        for (int f = 0; f < Ff; f++) s += W[k * HFt + h * Ff + f] * a[h * Ff + f];
        g_u[k * 16 + j] = s;
        if (id < 16) {
            const float* bb = (j < 8) ? bsrc : bdst;
            float s2 = 0.f;
            for (int f = 0; f < Ff; f++) s2 += bb[h * Ff + f] * a[h * Ff + f];
            g_c[id] = s2;
        }
    } else {
        int idx = (b - 32) * 256 + tid;          // [n][k]
        int n = idx >> 9, k = idx & 511;
        g_Bh[idx] = __float2half_rn(Wval[k * HFt + n]);
    }
}

// ---------------- feat -> fp16 + edge histogram (MLP=2 per thread) ----------------
__global__ void __launch_bounds__(256) k_convert(const float* __restrict__ feat,
                                                 const int* __restrict__ dst) {
    size_t base = (size_t)blockIdx.x * 512 + threadIdx.x;   // two float4s per thread
    size_t idx0 = base, idx1 = base + 256;
    if (idx0 < Ee) atomicAdd(&g_deg[dst[idx0]], 1);
    if (idx1 < Ee) atomicAdd(&g_deg[dst[idx1]], 1);
    size_t row0 = idx0 >> 7, row1 = idx1 >> 7;
    float4 v0 = make_float4(0.f, 0.f, 0.f, 0.f), v1 = v0;
    if (row0 < Nn) v0 = ((const float4*)feat)[idx0];
    if (row1 < Nn) v1 = ((const float4*)feat)[idx1];
    __half2 a0 = __floats2half2_rn(v0.x, v0.y);
    __half2 a1 = __floats2half2_rn(v0.z, v0.w);
    __half2 b0 = __floats2half2_rn(v1.x, v1.y);
    __half2 b1 = __floats2half2_rn(v1.z, v1.w);
    ((uint2*)g_Ah)[idx0] = make_uint2(*reinterpret_cast<uint32_t*>(&a0),
                                      *reinterpret_cast<uint32_t*>(&a1));
    ((uint2*)g_Ah)[idx1] = make_uint2(*reinterpret_cast<uint32_t*>(&b0),
                                      *reinterpret_cast<uint32_t*>(&b1));
}

// ---------------- 2-phase scan ----------------
__global__ void k_scan1() {
    __shared__ int sh[1024];
    int t = threadIdx.x;
    int i = blockIdx.x * 1024 + t;
    int v = (i < Nn) ? g_deg[i] : 0;
    sh[t] = v;
    __syncthreads();
    for (int off = 1; off < 1024; off <<= 1) {
        int x = (t >= off) ? sh[t - off] : 0;
        __syncthreads();
        sh[t] += x;
        __syncthreads();
    }
    if (i < Nn) g_row[i] = sh[t] - v;
    if (t == 1023) g_part[blockIdx.x] = sh[1023];
}
__global__ void k_scan3(int nblk) {
    __shared__ int sp[64];
    int t = threadIdx.x;
    if (t < 64) sp[t] = g_part[t];
    __syncthreads();
    int off = 0, total = 0;
    #pragma unroll
    for (int i = 0; i < 64; i++) {
        int v = sp[i];
        total += v;
        if (i < blockIdx.x) off += v;
    }
    int i = blockIdx.x * 1024 + t;
    if (i < Nn) {
        int x = g_row[i] + off;
        g_row[i] = x;
        g_pos[i] = x;
    }
    if (blockIdx.x == nblk - 1 && t == 0) g_row[Nn] = total;
}

__global__ void k_scatter(const int* __restrict__ src, const int* __restrict__ dst) {
    int e = blockIdx.x * blockDim.x + threadIdx.x;
    if (e < Ee) {
        int d = dst[e];
        int slot = atomicAdd(&g_pos[d], 1);
        g_csrc[slot] = src[e];
    }
}

// ---------------- skinny GEMM: el/er = feat(fp16) @ u + c ----------------
__global__ void __launch_bounds__(128) k_elr() {
    __shared__ float sA[128][33];
    __shared__ float sB[32][16];
    int tid = threadIdx.x;
    int rowBase = blockIdx.x * 128;
    float acc[16];
    #pragma unroll
    for (int j = 0; j < 16; j++) acc[j] = g_c[j];

    for (int kt = 0; kt < Kk; kt += 32) {
        #pragma unroll
        for (int i = 0; i < 8; i++) {
            int f4 = i * 128 + tid;
            int r = f4 >> 3, c4 = f4 & 7;
            uint2 u = ((const uint2*)g_Ah)[((size_t)(rowBase + r) * Kk + kt + c4 * 4) >> 2];
            float2 a = __half22float2(*reinterpret_cast<__half2*>(&u.x));
            float2 bb = __half22float2(*reinterpret_cast<__half2*>(&u.y));
            sA[r][c4 * 4 + 0] = a.x;  sA[r][c4 * 4 + 1] = a.y;
            sA[r][c4 * 4 + 2] = bb.x; sA[r][c4 * 4 + 3] = bb.y;
        }
        {
            int r = tid >> 2, c4 = tid & 3;
            float4 v = *(const float4*)&g_u[(kt + r) * 16 + c4 * 4];
            *(float4*)&sB[r][c4 * 4] = v;
        }
        __syncthreads();
        #pragma unroll
        for (int k = 0; k < 32; k++) {
            float f = sA[tid][k];
            float4 b0 = *(float4*)&sB[k][0];
            float4 b1 = *(float4*)&sB[k][4];
            float4 b2 = *(float4*)&sB[k][8];
            float4 b3 = *(float4*)&sB[k][12];
            acc[0] += f * b0.x; acc[1] += f * b0.y; acc[2] += f * b0.z; acc[3] += f * b0.w;
            acc[4] += f * b1.x; acc[5] += f * b1.y; acc[6] += f * b1.z; acc[7] += f * b1.w;
            acc[8] += f * b2.x; acc[9] += f * b2.y; acc[10] += f * b2.z; acc[11] += f * b2.w;
            acc[12] += f * b3.x; acc[13] += f * b3.y; acc[14] += f * b3.z; acc[15] += f * b3.w;
        }
        __syncthreads();
    }
    int n = rowBase + tid;
    if (n < Nn) {
        #pragma unroll
        for (int h = 0; h < 8; h++) {
            g_el[n * 8 + h] = acc[h];
            g_er[n * 8 + h] = acc[8 + h];
        }
    }
}

// ---------------- HMMA GEMM: BK=64, 8 chunks, double buffer, 2 CTAs/SM ----------------
#define PITCH 144
#define MAT_B (128 * PITCH)
#define STAGE_B (2 * MAT_B)
#define SMEM_GEMM (2 * STAGE_B)        // 73728

__global__ void __launch_bounds__(256, 2) k_gemm_mma(const float* __restrict__ bias, int nOff) {
    extern __shared__ char sm[];
    uint32_t sb = smem_u32(sm);

    const int tid = threadIdx.x;
    const int lane = tid & 31, wid = tid >> 5;
    const int wm = wid >> 1, wn = wid & 1;           // warp grid 4x2
    const int mBase = blockIdx.y * 128;
    const int nBase = (blockIdx.x + nOff) * 128;

    const int g8 = lane >> 3, lr = lane & 7;
    const int a_row = lr + ((g8 == 1 || g8 == 3) ? 8 : 0);
    const uint32_t a_kb = (g8 >= 2) ? 16 : 0;
    const int b_row = lr + ((g8 >= 2) ? 8 : 0);
    const uint32_t b_kb = (g8 & 1) ? 16 : 0;
    const uint32_t aAddr0 = sb + 0 * MAT_B + (wm * 32 + a_row) * PITCH + a_kb;
    const uint32_t bAddr0 = sb + 1 * MAT_B + (wn * 64 + b_row) * PITCH + b_kb;

    float acc[2][8][4];
    #pragma unroll
    for (int i = 0; i < 2; i++)
        #pragma unroll
        for (int j = 0; j < 8; j++)
            #pragma unroll
            for (int q = 0; q < 4; q++) acc[i][j][q] = 0.f;

    const __half* gp_i[8];
    uint32_t sd_i[8];
    #pragma unroll
    for (int i = 0; i < 8; i++) {
        int idx = tid + i * 256;
        int mat = idx >> 10;
        int rc = idx & 1023;
        int r = rc >> 3, ch = rc & 7;
        const __half* base = (mat == 0) ? g_Ah : g_Bh;
        int rowG = ((mat == 0) ? mBase : nBase) + r;
        gp_i[i] = base + (size_t)rowG * Kk + ch * 8;
        sd_i[i] = sb + mat * MAT_B + r * PITCH + ch * 16;
    }
    auto load_stage = [&](int c, int buf) {
        uint32_t bo = buf * STAGE_B;
        #pragma unroll
        for (int i = 0; i < 8; i++) cpa16(sd_i[i] + bo, gp_i[i] + c * 64);
    };

    load_stage(0, 0);
    cp_commit();

    for (int c = 0; c < 8; c++) {
        cp_wait<0>();
        __syncthreads();
        if (c + 1 < 8) {
            load_stage(c + 1, (c + 1) & 1);
            cp_commit();
        }

        const uint32_t stOff = (c & 1) * STAGE_B;
        #pragma unroll
        for (int ks = 0; ks < 4; ks++) {
            uint32_t kb = stOff + ks * 32;
            uint32_t ah[2][4], bh[4][4];
            #pragma unroll
            for (int mt = 0; mt < 2; mt++)
                ldmx4(ah[mt][0], ah[mt][1], ah[mt][2], ah[mt][3], aAddr0 + kb + mt * 16 * PITCH);
            #pragma unroll
            for (int nt = 0; nt < 4; nt++)
                ldmx4(bh[nt][0], bh[nt][1], bh[nt][2], bh[nt][3], bAddr0 + kb + nt * 16 * PITCH);
            #pragma unroll
            for (int mt = 0; mt < 2; mt++)
                #pragma unroll
                for (int nt = 0; nt < 4; nt++) {
                    mma16816(acc[mt][2 * nt + 0], ah[mt], bh[nt][0], bh[nt][1]);
                    mma16816(acc[mt][2 * nt + 1], ah[mt], bh[nt][2], bh[nt][3]);
                }
        }
    }

    const int qr = lane >> 2, qc = (lane & 3) * 2;
    #pragma unroll
    for (int mt = 0; mt < 2; mt++) {
        int row0 = mBase + wm * 32 + mt * 16 + qr;
        #pragma unroll
        for (int n8 = 0; n8 < 8; n8++) {
            int col = nBase + wn * 64 + n8 * 8 + qc;
            float bx = bias[col], by = bias[col + 1];
            if (row0 < Nn) {
                __half2 o = __floats2half2_rn(acc[mt][n8][0] + bx, acc[mt][n8][1] + by);
                *(__half2*)&g_featv[(size_t)row0 * HFt + col] = o;
            }
            if (row0 + 8 < Nn) {
                __half2 o = __floats2half2_rn(acc[mt][n8][2] + bx, acc[mt][n8][3] + by);
                *(__half2*)&g_featv[(size_t)(row0 + 8) * HFt + col] = o;
            }
        }
    }
}

// ---------------- per-dst softmax + aggregation (head-half via hOff) ----------------
__global__ void __launch_bounds__(256) k_agg(float* __restrict__ out, int hOff) {
    int grp = threadIdx.x >> 6;                 // 4 nodes per block
    int n = blockIdx.x * 4 + grp;
    if (n >= Nn) return;
    int t = threadIdx.x & 63;
    int h = (t >> 4) + hOff;
    int colBase = h * 64 + (t & 15) * 4;

    int beg = g_row[n], end = g_row[n + 1];
    float er = g_er[n * 8 + h];

    float ssum = 0.f;
    for (int j = beg; j < end; j++) {
        float e = g_el[g_csrc[j] * 8 + h] + er;
        e = (e >= 0.f) ? e : NEG * e;
        ssum += __expf(e);
    }
    float rs = 1.0f / fmaxf(ssum, 1e-16f);

    float4 acc = make_float4(0.f, 0.f, 0.f, 0.f);
    int j = beg;
    for (; j + 2 <= end; j += 2) {
        int s0 = g_csrc[j], s1 = g_csrc[j + 1];
        float e0 = g_el[s0 * 8 + h] + er;
        float e1 = g_el[s1 * 8 + h] + er;
        e0 = (e0 >= 0.f) ? e0 : NEG * e0;
        e1 = (e1 >= 0.f) ? e1 : NEG * e1;
        float a0 = __expf(e0) * rs;
        float a1 = __expf(e1) * rs;
        uint2 u0 = *(const uint2*)&g_featv[(size_t)s0 * HFt + colBase];
        uint2 u1 = *(const uint2*)&g_featv[(size_t)s1 * HFt + colBase];
        float2 p0 = __half22float2(*(__half2*)&u0.x);
        float2 p1 = __half22float2(*(__half2*)&u0.y);
        float2 q0 = __half22float2(*(__half2*)&u1.x);
        float2 q1 = __half22float2(*(__half2*)&u1.y);
        acc.x += a0 * p0.x + a1 * q0.x;
        acc.y += a0 * p0.y + a1 * q0.y;
        acc.z += a0 * p1.x + a1 * q1.x;
        acc.w += a0 * p1.y + a1 * q1.y;
    }
    if (j < end) {
        int s0 = g_csrc[j];
        float e0 = g_el[s0 * 8 + h] + er;
        e0 = (e0 >= 0.f) ? e0 : NEG * e0;
        float a0 = __expf(e0) * rs;
        uint2 u0 = *(const uint2*)&g_featv[(size_t)s0 * HFt + colBase];
        float2 p0 = __half22float2(*(__half2*)&u0.x);
        float2 p1 = __half22float2(*(__half2*)&u0.y);
        acc.x += a0 * p0.x; acc.y += a0 * p0.y; acc.z += a0 * p1.x; acc.w += a0 * p1.y;
    }
    *(float4*)&out[(size_t)n * HFt + colBase] = acc;
}

// ---------------- launch: R13 schedule (best known) ----------------
extern "C" void kernel_launch(void* const* d_in, const int* in_sizes, int n_in,
                              void* d_out, int out_size) {
    const float* feat = (const float*)d_in[0];
    const int*   src  = (const int*)d_in[1];
    const int*   dst  = (const int*)d_in[2];
    const float* Wsrc = (const float*)d_in[3];
    const float* bsrc = (const float*)d_in[4];
    const float* Wdst = (const float*)d_in[5];
    const float* bdst = (const float*)d_in[6];
    const float* Wval = (const float*)d_in[7];
    const float* bval = (const float*)d_in[8];
    const float* al   = (const float*)d_in[9];
    const float* ar   = (const float*)d_in[10];
    float* out = (float*)d_out;

    static cudaStream_t s1 = nullptr;
    static cudaEvent_t evRoot = nullptr, evSetup = nullptr, evConv = nullptr,
                       evSide = nullptr, evG0 = nullptr, evA0 = nullptr;
    if (!s1) {
        cudaFuncSetAttribute(k_gemm_mma, cudaFuncAttributeMaxDynamicSharedMemorySize, SMEM_GEMM);
        cudaStreamCreateWithFlags(&s1, cudaStreamNonBlocking);
        cudaEventCreateWithFlags(&evRoot, cudaEventDisableTiming);
        cudaEventCreateWithFlags(&evSetup, cudaEventDisableTiming);
        cudaEventCreateWithFlags(&evConv, cudaEventDisableTiming);
        cudaEventCreateWithFlags(&evSide, cudaEventDisableTiming);
        cudaEventCreateWithFlags(&evG0, cudaEventDisableTiming);
        cudaEventCreateWithFlags(&evA0, cudaEventDisableTiming);
    }

    int nscan = (Nn + 1023) / 1024;
    dim3 gg(2, NnP / 128);   // one N-half per launch

    // main: zero deg (capture root)
    k_zdeg<<<196, 256>>>();
    cudaEventRecord(evRoot, 0);

    // side: setup (weights only), concurrent with convert
    cudaStreamWaitEvent(s1, evRoot, 0);
    k_setup<<<1056, 256, 0, s1>>>(Wsrc, Wdst, al, ar, bsrc, bdst, Wval);
    cudaEventRecord(evSetup, s1);

    // main: convert (histogram + fp16 A, MLP=2)
    k_convert<<<(NnP * Kk / 8) / 256, 256>>>(feat, dst);
    cudaEventRecord(evConv, 0);

    // main: GEMM half 0 (4th submitted kernel — ncu target)
    cudaStreamWaitEvent(0, evSetup, 0);
    k_gemm_mma<<<gg, 256, SMEM_GEMM>>>(bval, 0);
    cudaEventRecord(evG0, 0);

    // side: CSR build + edge logits
    cudaStreamWaitEvent(s1, evConv, 0);
    k_scan1<<<nscan, 1024, 0, s1>>>();
    k_scan3<<<nscan, 1024, 0, s1>>>(nscan);
    k_scatter<<<(Ee + 255) / 256, 256, 0, s1>>>(src, dst);
    k_elr<<<NnP / 128, 128, 0, s1>>>();
    cudaEventRecord(evSide, s1);

    // side: agg heads [0,4) after featv half0 + side chain
    cudaStreamWaitEvent(s1, evG0, 0);
    k_agg<<<(Nn + 3) / 4, 256, 0, s1>>>(out, 0);
    cudaEventRecord(evA0, s1);

    // main: GEMM half 1 concurrent with agg half 0; then agg heads [4,8)
    k_gemm_mma<<<gg, 256, SMEM_GEMM>>>(bval, 2);
    cudaStreamWaitEvent(0, evSide, 0);
    k_agg<<<(Nn + 3) / 4, 256>>>(out, 4);

    // join
    cudaStreamWaitEvent(0, evA0, 0);
}

// round 16
// speedup vs baseline: 1.2931x; 1.0834x over previous
#include <cuda_runtime.h>
#include <cuda_fp16.h>
#include <cstdint>

#define Nn 50000
#define NnP 50048
#define Ee 400000
#define Kk 512
#define Hh 8
#define Ff 64
#define HFt 512
#define NEG 0.2f

// ---------------- device scratch ----------------
__device__ __align__(16) __half g_featv[(size_t)Nn * HFt];   // 51.2 MB fp16
__device__ __align__(16) __half g_Ah[(size_t)NnP * Kk];      // feat fp16
__device__ __align__(16) __half g_Bh[HFt * Kk];              // W_val^T fp16 [N][K]
__device__ float g_el[Nn * Hh];
__device__ float g_er[Nn * Hh];
__device__ float g_rs[Nn * Hh];        // per (node,head) reciprocal softmax denom
__device__ float g_u[Kk * 16];
__device__ float g_c[16];
__device__ int   g_deg[Nn];
__device__ int   g_row[Nn + 1];
__device__ int   g_pos[Nn];
__device__ int   g_csrc[Ee];
__device__ int   g_part[64];

// ---------------- ptx helpers ----------------
__device__ __forceinline__ uint32_t smem_u32(const void* p) {
    uint32_t a;
    asm("{ .reg .u64 t; cvta.to.shared.u64 t, %1; cvt.u32.u64 %0, t; }" : "=r"(a) : "l"(p));
    return a;
}
__device__ __forceinline__ void cpa16(uint32_t d, const void* s) {
    asm volatile("cp.async.cg.shared.global [%0], [%1], 16;" :: "r"(d), "l"(s));
}
__device__ __forceinline__ void cp_commit() {
    asm volatile("cp.async.commit_group;" ::: "memory");
}
template<int NN>
__device__ __forceinline__ void cp_wait() {
    asm volatile("cp.async.wait_group %0;" :: "n"(NN) : "memory");
}
__device__ __forceinline__ void ldmx4(uint32_t& r0, uint32_t& r1, uint32_t& r2, uint32_t& r3, uint32_t a) {
    asm volatile("ldmatrix.sync.aligned.m8n8.x4.shared.b16 {%0,%1,%2,%3}, [%4];"
                 : "=r"(r0), "=r"(r1), "=r"(r2), "=r"(r3) : "r"(a));
}
__device__ __forceinline__ void mma16816(float* d, const uint32_t* a, uint32_t b0, uint32_t b1) {
    asm volatile("mma.sync.aligned.m16n8k16.row.col.f32.f16.f16.f32 "
                 "{%0,%1,%2,%3}, {%4,%5,%6,%7}, {%8,%9}, {%0,%1,%2,%3};"
                 : "+f"(d[0]), "+f"(d[1]), "+f"(d[2]), "+f"(d[3])
                 : "r"(a[0]), "r"(a[1]), "r"(a[2]), "r"(a[3]), "r"(b0), "r"(b1));
}

// ---------------- zero deg + part ----------------
__global__ void k_zdeg() {
    int i = blockIdx.x * 256 + threadIdx.x;
    if (i < Nn) g_deg[i] = 0;
    if (blockIdx.x == 0 && threadIdx.x < 64) g_part[threadIdx.x] = 0;
}

// ---------------- setup: prep (u,c) + W_val transpose (weights only) ----------------
__global__ void k_setup(const float* __restrict__ Wsrc, const float* __restrict__ Wdst,
                        const float* __restrict__ al, const float* __restrict__ ar,
                        const float* __restrict__ bsrc, const float* __restrict__ bdst,
                        const float* __restrict__ Wval) {
    int b = blockIdx.x, tid = threadIdx.x;
    if (b < 32) {
        int id = b * 256 + tid;
        int k = id >> 4, j = id & 15, h = j & 7;
        const float* W = (j < 8) ? Wsrc : Wdst;
        const float* a = (j < 8) ? al : ar;
        float s = 0.f;
        #pragma unroll 8
        for (int f = 0; f < Ff; f++) s += W[k * HFt + h * Ff + f] * a[h * Ff + f];
        g_u[k * 16 + j] = s;
        if (id < 16) {
            const float* bb = (j < 8) ? bsrc : bdst;
            float s2 = 0.f;
            for (int f = 0; f < Ff; f++) s2 += bb[h * Ff + f] * a[h * Ff + f];
            g_c[id] = s2;
        }
    } else {
        int idx = (b - 32) * 256 + tid;          // [n][k]
        int n = idx >> 9, k = idx & 511;
        g_Bh[idx] = __float2half_rn(Wval[k * HFt + n]);
    }
}

// ---------------- feat -> fp16 + edge histogram (MLP=2 per thread) ----------------
__global__ void __launch_bounds__(256) k_convert(const float* __restrict__ feat,
                                                 const int* __restrict__ dst) {
    size_t base = (size_t)blockIdx.x * 512 + threadIdx.x;   // two float4s per thread
    size_t idx0 = base, idx1 = base + 256;
    if (idx0 < Ee) atomicAdd(&g_deg[dst[idx0]], 1);
    if (idx1 < Ee) atomicAdd(&g_deg[dst[idx1]], 1);
    size_t row0 = idx0 >> 7, row1 = idx1 >> 7;
    float4 v0 = make_float4(0.f, 0.f, 0.f, 0.f), v1 = v0;
    if (row0 < Nn) v0 = ((const float4*)feat)[idx0];
    if (row1 < Nn) v1 = ((const float4*)feat)[idx1];
    __half2 a0 = __floats2half2_rn(v0.x, v0.y);
    __half2 a1 = __floats2half2_rn(v0.z, v0.w);
    __half2 b0 = __floats2half2_rn(v1.x, v1.y);
    __half2 b1 = __floats2half2_rn(v1.z, v1.w);
    ((uint2*)g_Ah)[idx0] = make_uint2(*reinterpret_cast<uint32_t*>(&a0),
                                      *reinterpret_cast<uint32_t*>(&a1));
    ((uint2*)g_Ah)[idx1] = make_uint2(*reinterpret_cast<uint32_t*>(&b0),
                                      *reinterpret_cast<uint32_t*>(&b1));
}

// ---------------- 2-phase scan ----------------
__global__ void k_scan1() {
    __shared__ int sh[1024];
    int t = threadIdx.x;
    int i = blockIdx.x * 1024 + t;
    int v = (i < Nn) ? g_deg[i] : 0;
    sh[t] = v;
    __syncthreads();
    for (int off = 1; off < 1024; off <<= 1) {
        int x = (t >= off) ? sh[t - off] : 0;
        __syncthreads();
        sh[t] += x;
        __syncthreads();
    }
    if (i < Nn) g_row[i] = sh[t] - v;
    if (t == 1023) g_part[blockIdx.x] = sh[1023];
}
__global__ void k_scan3(int nblk) {
    __shared__ int sp[64];
    int t = threadIdx.x;
    if (t < 64) sp[t] = g_part[t];
    __syncthreads();
    int off = 0, total = 0;
    #pragma unroll
    for (int i = 0; i < 64; i++) {
        int v = sp[i];
        total += v;
        if (i < blockIdx.x) off += v;
    }
    int i = blockIdx.x * 1024 + t;
    if (i < Nn) {
        int x = g_row[i] + off;
        g_row[i] = x;
        g_pos[i] = x;
    }
    if (blockIdx.x == nblk - 1 && t == 0) g_row[Nn] = total;
}

__global__ void k_scatter(const int* __restrict__ src, const int* __restrict__ dst) {
    int e = blockIdx.x * blockDim.x + threadIdx.x;
    if (e < Ee) {
        int d = dst[e];
        int slot = atomicAdd(&g_pos[d], 1);
        g_csrc[slot] = src[e];
    }
}

// ---------------- skinny GEMM: el/er = feat(fp16) @ u + c ----------------
__global__ void __launch_bounds__(128) k_elr() {
    __shared__ float sA[128][33];
    __shared__ float sB[32][16];
    int tid = threadIdx.x;
    int rowBase = blockIdx.x * 128;
    float acc[16];
    #pragma unroll
    for (int j = 0; j < 16; j++) acc[j] = g_c[j];

    for (int kt = 0; kt < Kk; kt += 32) {
        #pragma unroll
        for (int i = 0; i < 8; i++) {
            int f4 = i * 128 + tid;
            int r = f4 >> 3, c4 = f4 & 7;
            uint2 u = ((const uint2*)g_Ah)[((size_t)(rowBase + r) * Kk + kt + c4 * 4) >> 2];
            float2 a = __half22float2(*reinterpret_cast<__half2*>(&u.x));
            float2 bb = __half22float2(*reinterpret_cast<__half2*>(&u.y));
            sA[r][c4 * 4 + 0] = a.x;  sA[r][c4 * 4 + 1] = a.y;
            sA[r][c4 * 4 + 2] = bb.x; sA[r][c4 * 4 + 3] = bb.y;
        }
        {
            int r = tid >> 2, c4 = tid & 3;
            float4 v = *(const float4*)&g_u[(kt + r) * 16 + c4 * 4];
            *(float4*)&sB[r][c4 * 4] = v;
        }
        __syncthreads();
        #pragma unroll
        for (int k = 0; k < 32; k++) {
            float f = sA[tid][k];
            float4 b0 = *(float4*)&sB[k][0];
            float4 b1 = *(float4*)&sB[k][4];
            float4 b2 = *(float4*)&sB[k][8];
            float4 b3 = *(float4*)&sB[k][12];
            acc[0] += f * b0.x; acc[1] += f * b0.y; acc[2] += f * b0.z; acc[3] += f * b0.w;
            acc[4] += f * b1.x; acc[5] += f * b1.y; acc[6] += f * b1.z; acc[7] += f * b1.w;
            acc[8] += f * b2.x; acc[9] += f * b2.y; acc[10] += f * b2.z; acc[11] += f * b2.w;
            acc[12] += f * b3.x; acc[13] += f * b3.y; acc[14] += f * b3.z; acc[15] += f * b3.w;
        }
        __syncthreads();
    }
    int n = rowBase + tid;
    if (n < Nn) {
        #pragma unroll
        for (int h = 0; h < 8; h++) {
            g_el[n * 8 + h] = acc[h];
            g_er[n * 8 + h] = acc[8 + h];
        }
    }
}

// ---------------- softmax normalizer: g_rs[n][h] (hidden under GEMM) ----------------
__global__ void __launch_bounds__(256) k_soft() {
    int gid = blockIdx.x * 256 + threadIdx.x;     // (n,h)
    if (gid >= Nn * Hh) return;
    int n = gid >> 3, h = gid & 7;
    int beg = g_row[n], end = g_row[n + 1];
    float er = g_er[gid];
    float ssum = 0.f;
    for (int j = beg; j < end; j++) {
        float e = g_el[g_csrc[j] * 8 + h] + er;
        e = (e >= 0.f) ? e : NEG * e;
        ssum += __expf(e);
    }
    g_rs[gid] = 1.0f / fmaxf(ssum, 1e-16f);
}

// ---------------- HMMA GEMM: BK=64, 8 chunks, double buffer, 2 CTAs/SM ----------------
#define PITCH 144
#define MAT_B (128 * PITCH)
#define STAGE_B (2 * MAT_B)
#define SMEM_GEMM (2 * STAGE_B)        // 73728

__global__ void __launch_bounds__(256, 2) k_gemm_mma(const float* __restrict__ bias, int nOff) {
    extern __shared__ char sm[];
    uint32_t sb = smem_u32(sm);

    const int tid = threadIdx.x;
    const int lane = tid & 31, wid = tid >> 5;
    const int wm = wid >> 1, wn = wid & 1;           // warp grid 4x2
    const int mBase = blockIdx.y * 128;
    const int nBase = (blockIdx.x + nOff) * 128;

    const int g8 = lane >> 3, lr = lane & 7;
    const int a_row = lr + ((g8 == 1 || g8 == 3) ? 8 : 0);
    const uint32_t a_kb = (g8 >= 2) ? 16 : 0;
    const int b_row = lr + ((g8 >= 2) ? 8 : 0);
    const uint32_t b_kb = (g8 & 1) ? 16 : 0;
    const uint32_t aAddr0 = sb + 0 * MAT_B + (wm * 32 + a_row) * PITCH + a_kb;
    const uint32_t bAddr0 = sb + 1 * MAT_B + (wn * 64 + b_row) * PITCH + b_kb;

    float acc[2][8][4];
    #pragma unroll
    for (int i = 0; i < 2; i++)
        #pragma unroll
        for (int j = 0; j < 8; j++)
            #pragma unroll
            for (int q = 0; q < 4; q++) acc[i][j][q] = 0.f;

    const __half* gp_i[8];
    uint32_t sd_i[8];
    #pragma unroll
    for (int i = 0; i < 8; i++) {
        int idx = tid + i * 256;
        int mat = idx >> 10;
        int rc = idx & 1023;
        int r = rc >> 3, ch = rc & 7;
        const __half* base = (mat == 0) ? g_Ah : g_Bh;
        int rowG = ((mat == 0) ? mBase : nBase) + r;
        gp_i[i] = base + (size_t)rowG * Kk + ch * 8;
        sd_i[i] = sb + mat * MAT_B + r * PITCH + ch * 16;
    }
    auto load_stage = [&](int c, int buf) {
        uint32_t bo = buf * STAGE_B;
        #pragma unroll
        for (int i = 0; i < 8; i++) cpa16(sd_i[i] + bo, gp_i[i] + c * 64);
    };

    load_stage(0, 0);
    cp_commit();

    for (int c = 0; c < 8; c++) {
        cp_wait<0>();
        __syncthreads();
        if (c + 1 < 8) {
            load_stage(c + 1, (c + 1) & 1);
            cp_commit();
        }

        const uint32_t stOff = (c & 1) * STAGE_B;
        #pragma unroll
        for (int ks = 0; ks < 4; ks++) {
            uint32_t kb = stOff + ks * 32;
            uint32_t ah[2][4], bh[4][4];
            #pragma unroll
            for (int mt = 0; mt < 2; mt++)
                ldmx4(ah[mt][0], ah[mt][1], ah[mt][2], ah[mt][3], aAddr0 + kb + mt * 16 * PITCH);
            #pragma unroll
            for (int nt = 0; nt < 4; nt++)
                ldmx4(bh[nt][0], bh[nt][1], bh[nt][2], bh[nt][3], bAddr0 + kb + nt * 16 * PITCH);
            #pragma unroll
            for (int mt = 0; mt < 2; mt++)
                #pragma unroll
                for (int nt = 0; nt < 4; nt++) {
                    mma16816(acc[mt][2 * nt + 0], ah[mt], bh[nt][0], bh[nt][1]);
                    mma16816(acc[mt][2 * nt + 1], ah[mt], bh[nt][2], bh[nt][3]);
                }
        }
    }

    const int qr = lane >> 2, qc = (lane & 3) * 2;
    #pragma unroll
    for (int mt = 0; mt < 2; mt++) {
        int row0 = mBase + wm * 32 + mt * 16 + qr;
        #pragma unroll
        for (int n8 = 0; n8 < 8; n8++) {
            int col = nBase + wn * 64 + n8 * 8 + qc;
            float bx = bias[col], by = bias[col + 1];
            if (row0 < Nn) {
                __half2 o = __floats2half2_rn(acc[mt][n8][0] + bx, acc[mt][n8][1] + by);
                *(__half2*)&g_featv[(size_t)row0 * HFt + col] = o;
            }
            if (row0 + 8 < Nn) {
                __half2 o = __floats2half2_rn(acc[mt][n8][2] + bx, acc[mt][n8][3] + by);
                *(__half2*)&g_featv[(size_t)(row0 + 8) * HFt + col] = o;
            }
        }
    }
}

// ---------------- gather-only aggregation (normalizer precomputed) ----------------
__global__ void __launch_bounds__(256) k_agg(float* __restrict__ out, int hOff) {
    int grp = threadIdx.x >> 6;                 // 4 nodes per block
    int n = blockIdx.x * 4 + grp;
    if (n >= Nn) return;
    int t = threadIdx.x & 63;
    int h = (t >> 4) + hOff;
    int colBase = h * 64 + (t & 15) * 4;

    int beg = g_row[n], end = g_row[n + 1];
    float er = g_er[n * 8 + h];
    float rs = g_rs[n * 8 + h];

    float4 acc = make_float4(0.f, 0.f, 0.f, 0.f);
    int j = beg;
    for (; j + 2 <= end; j += 2) {
        int s0 = g_csrc[j], s1 = g_csrc[j + 1];
        float e0 = g_el[s0 * 8 + h] + er;
        float e1 = g_el[s1 * 8 + h] + er;
        e0 = (e0 >= 0.f) ? e0 : NEG * e0;
        e1 = (e1 >= 0.f) ? e1 : NEG * e1;
        float a0 = __expf(e0) * rs;
        float a1 = __expf(e1) * rs;
        uint2 u0 = *(const uint2*)&g_featv[(size_t)s0 * HFt + colBase];
        uint2 u1 = *(const uint2*)&g_featv[(size_t)s1 * HFt + colBase];
        float2 p0 = __half22float2(*(__half2*)&u0.x);
        float2 p1 = __half22float2(*(__half2*)&u0.y);
        float2 q0 = __half22float2(*(__half2*)&u1.x);
        float2 q1 = __half22float2(*(__half2*)&u1.y);
        acc.x += a0 * p0.x + a1 * q0.x;
        acc.y += a0 * p0.y + a1 * q0.y;
        acc.z += a0 * p1.x + a1 * q1.x;
        acc.w += a0 * p1.y + a1 * q1.y;
    }
    if (j < end) {
        int s0 = g_csrc[j];
        float e0 = g_el[s0 * 8 + h] + er;
        e0 = (e0 >= 0.f) ? e0 : NEG * e0;
        float a0 = __expf(e0) * rs;
        uint2 u0 = *(const uint2*)&g_featv[(size_t)s0 * HFt + colBase];
        float2 p0 = __half22float2(*(__half2*)&u0.x);
        float2 p1 = __half22float2(*(__half2*)&u0.y);
        acc.x += a0 * p0.x; acc.y += a0 * p0.y; acc.z += a0 * p1.x; acc.w += a0 * p1.y;
    }
    *(float4*)&out[(size_t)n * HFt + colBase] = acc;
}

// ---------------- launch: R15 schedule + hoisted softmax ----------------
extern "C" void kernel_launch(void* const* d_in, const int* in_sizes, int n_in,
                              void* d_out, int out_size) {
    const float* feat = (const float*)d_in[0];
    const int*   src  = (const int*)d_in[1];
    const int*   dst  = (const int*)d_in[2];
    const float* Wsrc = (const float*)d_in[3];
    const float* bsrc = (const float*)d_in[4];
    const float* Wdst = (const float*)d_in[5];
    const float* bdst = (const float*)d_in[6];
    const float* Wval = (const float*)d_in[7];
    const float* bval = (const float*)d_in[8];
    const float* al   = (const float*)d_in[9];
    const float* ar   = (const float*)d_in[10];
    float* out = (float*)d_out;

    static cudaStream_t s1 = nullptr;
    static cudaEvent_t evRoot = nullptr, evSetup = nullptr, evConv = nullptr,
                       evSide = nullptr, evG0 = nullptr, evA0 = nullptr;
    if (!s1) {
        cudaFuncSetAttribute(k_gemm_mma, cudaFuncAttributeMaxDynamicSharedMemorySize, SMEM_GEMM);
        cudaStreamCreateWithFlags(&s1, cudaStreamNonBlocking);
        cudaEventCreateWithFlags(&evRoot, cudaEventDisableTiming);
        cudaEventCreateWithFlags(&evSetup, cudaEventDisableTiming);
        cudaEventCreateWithFlags(&evConv, cudaEventDisableTiming);
        cudaEventCreateWithFlags(&evSide, cudaEventDisableTiming);
        cudaEventCreateWithFlags(&evG0, cudaEventDisableTiming);
        cudaEventCreateWithFlags(&evA0, cudaEventDisableTiming);
    }

    int nscan = (Nn + 1023) / 1024;
    dim3 gg(2, NnP / 128);   // one N-half per launch

    // main: zero deg (capture root)
    k_zdeg<<<196, 256>>>();
    cudaEventRecord(evRoot, 0);

    // side: setup (weights only), concurrent with convert
    cudaStreamWaitEvent(s1, evRoot, 0);
    k_setup<<<1056, 256, 0, s1>>>(Wsrc, Wdst, al, ar, bsrc, bdst, Wval);
    cudaEventRecord(evSetup, s1);

    // main: convert (histogram + fp16 A, MLP=2)
    k_convert<<<(NnP * Kk / 8) / 256, 256>>>(feat, dst);
    cudaEventRecord(evConv, 0);

    // main: GEMM half 0 (4th submitted kernel — ncu target)
    cudaStreamWaitEvent(0, evSetup, 0);
    k_gemm_mma<<<gg, 256, SMEM_GEMM>>>(bval, 0);
    cudaEventRecord(evG0, 0);

    // side: CSR build + edge logits + softmax normalizers (all hidden under GEMM)
    cudaStreamWaitEvent(s1, evConv, 0);
    k_scan1<<<nscan, 1024, 0, s1>>>();
    k_scan3<<<nscan, 1024, 0, s1>>>(nscan);
    k_scatter<<<(Ee + 255) / 256, 256, 0, s1>>>(src, dst);
    k_elr<<<NnP / 128, 128, 0, s1>>>();
    k_soft<<<(Nn * Hh + 255) / 256, 256, 0, s1>>>();
    cudaEventRecord(evSide, s1);

    // side: agg heads [0,4) (gather-only) after featv half0 + side chain
    cudaStreamWaitEvent(s1, evG0, 0);
    k_agg<<<(Nn + 3) / 4, 256, 0, s1>>>(out, 0);
    cudaEventRecord(evA0, s1);

    // main: GEMM half 1 concurrent with agg half 0; then agg heads [4,8)
    k_gemm_mma<<<gg, 256, SMEM_GEMM>>>(bval, 2);
    cudaStreamWaitEvent(0, evSide, 0);
    k_agg<<<(Nn + 3) / 4, 256>>>(out, 4);

    // join
    cudaStreamWaitEvent(0, evA0, 0);
}